// round 2
// baseline (speedup 1.0000x reference)
#include <cuda_runtime.h>
#include <math.h>

#define BATCH 2
#define SEQ   2048
#define HEADS 16
#define HD    64
#define DM    1024
#define BH    (BATCH*HEADS)

// Scratch for Q,K,V in [b,h,n,d] layout (device BSS — no allocation)
__device__ float g_q[BH * SEQ * HD];
__device__ float g_k[BH * SEQ * HD];
__device__ float g_v[BH * SEQ * HD];

// ---------------------------------------------------------------------------
// Kernel 1: QKV projection. C[4096,3072] = A[4096,1024] @ W[1024,3072] + bias
// Scatters into g_q/g_k/g_v with [b,h,n,d] layout; folds 1/sqrt(64) into Q.
// Tile: BM=128, BN=64, BK=16. 256 threads, per-thread 8x4 microtile.
// ---------------------------------------------------------------------------
#define BM 128
#define BN 64
#define BK 16

__global__ __launch_bounds__(256) void qkv_gemm(const float* __restrict__ A,
                                                const float* __restrict__ W,
                                                const float* __restrict__ bias) {
    __shared__ __align__(16) float Ast[BK][BM + 4]; // transposed A, stride 132
    __shared__ __align__(16) float Bs[BK][BN + 4];  // stride 68

    const int tid = threadIdx.x;
    const int tx = tid & 15;
    const int ty = tid >> 4;
    const int bm = blockIdx.y * BM;
    const int bn = blockIdx.x * BN;

    float acc[8][4] = {};

    for (int k0 = 0; k0 < DM; k0 += BK) {
        #pragma unroll
        for (int i = 0; i < 8; i++) {
            int idx = tid + i * 256;           // 2048 = 128*16
            int r = idx >> 4, c = idx & 15;
            Ast[c][r] = A[(bm + r) * DM + k0 + c];
        }
        #pragma unroll
        for (int i = 0; i < 4; i++) {
            int idx = tid + i * 256;           // 1024 = 16*64
            int r = idx >> 6, c = idx & 63;
            Bs[r][c] = W[(k0 + r) * 3072 + bn + c];
        }
        __syncthreads();

        #pragma unroll
        for (int kk = 0; kk < BK; kk++) {
            float4 a0 = *reinterpret_cast<const float4*>(&Ast[kk][ty * 8]);
            float4 a1 = *reinterpret_cast<const float4*>(&Ast[kk][ty * 8 + 4]);
            float4 b0 = *reinterpret_cast<const float4*>(&Bs[kk][tx * 4]);
            float av[8] = {a0.x, a0.y, a0.z, a0.w, a1.x, a1.y, a1.z, a1.w};
            float bv[4] = {b0.x, b0.y, b0.z, b0.w};
            #pragma unroll
            for (int i = 0; i < 8; i++)
                #pragma unroll
                for (int j = 0; j < 4; j++)
                    acc[i][j] += av[i] * bv[j];
        }
        __syncthreads();
    }

    // Epilogue: bias add + scatter to Q/K/V buffers
    #pragma unroll
    for (int i = 0; i < 8; i++) {
        int row = bm + ty * 8 + i;         // 0..4095
        int bt  = row >> 11;               // batch
        int tok = row & 2047;
        #pragma unroll
        for (int j = 0; j < 4; j++) {
            int col = bn + tx * 4 + j;     // 0..3071
            float val = acc[i][j] + bias[col];
            int sec = col >> 10;           // 0=Q, 1=K, 2=V
            int rem = col & 1023;
            int h = rem >> 6;
            int ch = rem & 63;
            long dst = (((long)(bt * HEADS + h)) * SEQ + tok) * HD + ch;
            if (sec == 0)      g_q[dst] = val * 0.125f;  // fold 1/sqrt(64)
            else if (sec == 1) g_k[dst] = val;
            else               g_v[dst] = val;
        }
    }
}

// ---------------------------------------------------------------------------
// Kernel 2: flash attention. One CTA per (bh, 64-query tile).
// 256 threads; per-thread 4x4 microtile of S and O. K-tiles of 64.
// Dynamic smem: Qt[64][68] + Kt[64][68] + Vs[64][68]; P reuses Kt's buffer.
// ---------------------------------------------------------------------------
#define SM_STRIDE 68

__global__ __launch_bounds__(256) void attn_kernel(float* __restrict__ out) {
    extern __shared__ __align__(16) float smem[];
    float* Qt = smem;                      // [ch][q]   64 x 68
    float* Kt = smem + 64 * SM_STRIDE;     // [ch][k]   64 x 68  (reused as P[q][k])
    float* Vs = smem + 2 * 64 * SM_STRIDE; // [k][d]    64 x 68

    const int tid = threadIdx.x;
    const int tx = tid & 15;
    const int ty = tid >> 4;
    const int bh = blockIdx.y;
    const int q0 = blockIdx.x * 64;

    const float* Qp = g_q + (long)bh * SEQ * HD;
    const float* Kp = g_k + (long)bh * SEQ * HD;
    const float* Vp = g_v + (long)bh * SEQ * HD;

    // Load Q tile transposed: Qt[ch][q]
    #pragma unroll
    for (int i = 0; i < 16; i++) {
        int idx = tid + i * 256;           // 4096 = 64*64
        int r = idx >> 6, c = idx & 63;
        Qt[c * SM_STRIDE + r] = Qp[(q0 + r) * HD + c];
    }

    float o[4][4] = {};
    float m[4], l[4];
    #pragma unroll
    for (int i = 0; i < 4; i++) { m[i] = -1e30f; l[i] = 0.0f; }
    __syncthreads();

    for (int kt = 0; kt < SEQ; kt += 64) {
        // Load K (transposed) and V tiles
        #pragma unroll
        for (int i = 0; i < 16; i++) {
            int idx = tid + i * 256;
            int r = idx >> 6, c = idx & 63;
            Kt[c * SM_STRIDE + r] = Kp[(kt + r) * HD + c];
            Vs[r * SM_STRIDE + c] = Vp[(kt + r) * HD + c];
        }
        __syncthreads();

        // S = Q K^T  (scale already folded into Q)
        float s[4][4] = {};
        #pragma unroll
        for (int kk = 0; kk < HD; kk++) {
            float4 qa = *reinterpret_cast<const float4*>(&Qt[kk * SM_STRIDE + ty * 4]);
            float4 kb = *reinterpret_cast<const float4*>(&Kt[kk * SM_STRIDE + tx * 4]);
            float qv[4] = {qa.x, qa.y, qa.z, qa.w};
            float kv[4] = {kb.x, kb.y, kb.z, kb.w};
            #pragma unroll
            for (int i = 0; i < 4; i++)
                #pragma unroll
                for (int j = 0; j < 4; j++)
                    s[i][j] += qv[i] * kv[j];
        }
        __syncthreads();  // all Kt reads done before P overwrites it

        // Online softmax + write P into Kt's buffer (as P[q][k])
        #pragma unroll
        for (int i = 0; i < 4; i++) {
            float tm = s[i][0];
            #pragma unroll
            for (int j = 1; j < 4; j++) tm = fmaxf(tm, s[i][j]);
            #pragma unroll
            for (int off = 8; off > 0; off >>= 1)
                tm = fmaxf(tm, __shfl_xor_sync(0xffffffffu, tm, off, 32));

            float mnew = fmaxf(m[i], tm);
            float alpha = __expf(m[i] - mnew);
            m[i] = mnew;

            float rs = 0.0f;
            #pragma unroll
            for (int j = 0; j < 4; j++) {
                s[i][j] = __expf(s[i][j] - mnew);
                rs += s[i][j];
            }
            #pragma unroll
            for (int off = 8; off > 0; off >>= 1)
                rs += __shfl_xor_sync(0xffffffffu, rs, off, 32);
            l[i] = l[i] * alpha + rs;

            #pragma unroll
            for (int j = 0; j < 4; j++) o[i][j] *= alpha;

            *reinterpret_cast<float4*>(&Kt[(ty * 4 + i) * SM_STRIDE + tx * 4]) =
                make_float4(s[i][0], s[i][1], s[i][2], s[i][3]);
        }
        __syncthreads();

        // O += P @ V
        #pragma unroll
        for (int kk = 0; kk < 64; kk++) {
            float pa[4];
            #pragma unroll
            for (int i = 0; i < 4; i++) pa[i] = Kt[(ty * 4 + i) * SM_STRIDE + kk];
            float4 vb4 = *reinterpret_cast<const float4*>(&Vs[kk * SM_STRIDE + tx * 4]);
            float vv[4] = {vb4.x, vb4.y, vb4.z, vb4.w};
            #pragma unroll
            for (int i = 0; i < 4; i++)
                #pragma unroll
                for (int j = 0; j < 4; j++)
                    o[i][j] += pa[i] * vv[j];
        }
        __syncthreads();
    }

    // Epilogue: normalize and write [b, n, h*64 + d]
    const int b = bh >> 4;
    const int h = bh & 15;
    #pragma unroll
    for (int i = 0; i < 4; i++) {
        float inv = 1.0f / l[i];
        int tok = q0 + ty * 4 + i;
        long base = ((long)(b * SEQ + tok)) * DM + h * HD + tx * 4;
        *reinterpret_cast<float4*>(&out[base]) =
            make_float4(o[i][0] * inv, o[i][1] * inv, o[i][2] * inv, o[i][3] * inv);
    }
}

// ---------------------------------------------------------------------------
extern "C" void kernel_launch(void* const* d_in, const int* in_sizes, int n_in,
                              void* d_out, int out_size) {
    const float* tokens = (const float*)d_in[0];   // [2,2048,1024]
    const float* w_qkv  = (const float*)d_in[1];   // [1024,3072]
    const float* b_qkv  = (const float*)d_in[2];   // [3072]
    float* out = (float*)d_out;                    // [2,2048,1024]

    const int attn_smem = 3 * 64 * SM_STRIDE * (int)sizeof(float); // 52224 B
    cudaFuncSetAttribute(attn_kernel,
                         cudaFuncAttributeMaxDynamicSharedMemorySize, attn_smem);

    dim3 g1(3072 / BN, 4096 / BM);   // (48, 32)
    qkv_gemm<<<g1, 256>>>(tokens, w_qkv, b_qkv);

    dim3 g2(SEQ / 64, BH);           // (32, 32)
    attn_kernel<<<g2, 256, attn_smem>>>(out);
}